// round 9
// baseline (speedup 1.0000x reference)
#include <cuda_runtime.h>
#include <cstdint>

#define BATCH  8
#define HWDIM  64
#define CCH    256
#define RED    64
#define EE     144     // K*K*G = 9*16
#define NTHR   512

// ---- smem layout (float offsets) ----
#define XH_STRIDE  260
#define OFF_XH     0                    // 100*260 = 26000
#define OFF_W1     26000                // 256*68 = 17408 (overlaid by WGT after stage1)
#define W1_STRIDE  68
#define OFF_WGT    26000                // 64*145 = 9280
#define WGT_STRIDE 145
#define OFF_W2     43408                // 64*152 = 9728
#define W2_STRIDE  152
#define OFF_MID    53136                // 64*68 = 4352
#define MID_STRIDE 68
#define OFF_B1     57488                // 64
#define OFF_B2     57552                // 144
#define SMEM_FLOATS 57696
#define SMEM_BYTES (SMEM_FLOATS * 4)    // 230784 B <= 227KB limit, 1 CTA/SM

// m16n8k8 tf32 mma: D += A(16x8 row) * B(8x8 col)
__device__ __forceinline__ void mma_tf32(float d[4],
    uint32_t a0, uint32_t a1, uint32_t a2, uint32_t a3,
    uint32_t b0, uint32_t b1)
{
    asm volatile(
        "mma.sync.aligned.m16n8k8.row.col.f32.tf32.tf32.f32 "
        "{%0,%1,%2,%3}, {%4,%5,%6,%7}, {%8,%9}, {%0,%1,%2,%3};"
        : "+f"(d[0]), "+f"(d[1]), "+f"(d[2]), "+f"(d[3])
        : "r"(a0), "r"(a1), "r"(a2), "r"(a3), "r"(b0), "r"(b1));
}

// split v into tf32-truncated hi (matches HW truncation) + exact residual lo
__device__ __forceinline__ void tf32_split(float v, uint32_t& hi, uint32_t& lo)
{
    uint32_t h = __float_as_uint(v) & 0xFFFFE000u;
    hi = h;
    lo = __float_as_uint(v - __uint_as_float(h));
}

__global__ void __launch_bounds__(NTHR, 1)
invo_mma_kernel(const float* __restrict__ x,
                const float* __restrict__ W1,
                const float* __restrict__ b1,
                const float* __restrict__ W2,
                const float* __restrict__ b2,
                float* __restrict__ out)
{
    extern __shared__ float s[];
    const int t  = threadIdx.x;
    const int bb = blockIdx.z;
    const int h0 = blockIdx.y * 8;
    const int w0 = blockIdx.x * 8;

    // ---- Phase 0: halo 10x10x256 (zero-padded), W1, W2, biases ----
    #pragma unroll
    for (int it = 0; it < 13; it++) {
        int i4 = t + it * NTHR;            // 0..6399 float4s
        if (i4 < 6400) {
            int c4 = i4 & 63;
            int sp = i4 >> 6;              // 0..99
            int r  = sp / 10;
            int cl = sp - r * 10;
            int gh = h0 - 1 + r;
            int gw = w0 - 1 + cl;
            float4 v = make_float4(0.f, 0.f, 0.f, 0.f);
            if ((unsigned)gh < HWDIM && (unsigned)gw < HWDIM)
                v = *(const float4*)(x + ((size_t)((bb * HWDIM + gh) * HWDIM + gw) * CCH) + c4 * 4);
            *(float4*)(s + OFF_XH + sp * XH_STRIDE + c4 * 4) = v;
        }
    }
    #pragma unroll
    for (int it = 0; it < 8; it++) {       // W1 [256 k][64 n] -> stride 68
        int i4 = t + it * NTHR;            // 0..4095
        int k  = i4 >> 4, n4 = i4 & 15;
        float4 v = *(const float4*)(W1 + i4 * 4);
        *(float4*)(s + OFF_W1 + k * W1_STRIDE + n4 * 4) = v;
    }
    #pragma unroll
    for (int it = 0; it < 5; it++) {       // W2 [64 d][144 e] -> stride 152
        int i4 = t + it * NTHR;            // 0..2303
        if (i4 < 2304) {
            int d = i4 / 36, e4 = i4 - d * 36;
            float4 v = *(const float4*)(W2 + i4 * 4);
            *(float4*)(s + OFF_W2 + d * W2_STRIDE + e4 * 4) = v;
        }
    }
    if (t < RED) s[OFF_B1 + t] = b1[t];
    else if (t >= 128 && t < 128 + EE) s[OFF_B2 + (t - 128)] = b2[t - 128];
    __syncthreads();

    const int warp = t >> 5, lane = t & 31;
    const int gid = lane >> 2, t4 = lane & 3;

    // ---- Stage 1: mid[64px][64] = x @ W1 + b1   (3-term tf32, 2 accumulators) ----
    // 16 warps: (warp>>2) = m-tile (16 rows), (warp&3) = n-quarter (2 ntiles of 8)
    {
        const int m0 = (warp >> 2) * 16;
        const int nb = (warp & 3) * 16;
        const int px0 = m0 + gid, px1 = px0 + 8;
        const int sp0 = OFF_XH + (((px0 >> 3) + 1) * 10 + (px0 & 7) + 1) * XH_STRIDE;
        const int sp1 = OFF_XH + (((px1 >> 3) + 1) * 10 + (px1 & 7) + 1) * XH_STRIDE;
        const int bp0 = OFF_W1 + t4 * W1_STRIDE + nb + gid;        // + k0*W1_STRIDE (+ nt*8)
        float Dm[2][4], Dc[2][4];
        #pragma unroll
        for (int nt = 0; nt < 2; nt++)
            #pragma unroll
            for (int i = 0; i < 4; i++) { Dm[nt][i] = 0.f; Dc[nt][i] = 0.f; }

        float a_cur[4], b_cur[2][2];
        a_cur[0] = s[sp0 + t4];       a_cur[1] = s[sp1 + t4];
        a_cur[2] = s[sp0 + t4 + 4];   a_cur[3] = s[sp1 + t4 + 4];
        #pragma unroll
        for (int nt = 0; nt < 2; nt++) {
            b_cur[nt][0] = s[bp0 + nt * 8];
            b_cur[nt][1] = s[bp0 + 4 * W1_STRIDE + nt * 8];
        }

        #pragma unroll 4
        for (int k0 = 0; k0 < CCH; k0 += 8) {
            // prefetch next k-step
            float a_nxt[4], b_nxt[2][2];
            if (k0 + 8 < CCH) {
                a_nxt[0] = s[sp0 + k0 + 8 + t4];       a_nxt[1] = s[sp1 + k0 + 8 + t4];
                a_nxt[2] = s[sp0 + k0 + 12 + t4];      a_nxt[3] = s[sp1 + k0 + 12 + t4];
                #pragma unroll
                for (int nt = 0; nt < 2; nt++) {
                    b_nxt[nt][0] = s[bp0 + (k0 + 8) * W1_STRIDE + nt * 8];
                    b_nxt[nt][1] = s[bp0 + (k0 + 12) * W1_STRIDE + nt * 8];
                }
            }
            uint32_t ah[4], al[4];
            #pragma unroll
            for (int i = 0; i < 4; i++) tf32_split(a_cur[i], ah[i], al[i]);
            #pragma unroll
            for (int nt = 0; nt < 2; nt++) {
                uint32_t bh0, bl0, bh1, bl1;
                tf32_split(b_cur[nt][0], bh0, bl0);
                tf32_split(b_cur[nt][1], bh1, bl1);
                mma_tf32(Dm[nt], ah[0], ah[1], ah[2], ah[3], bh0, bh1);
                mma_tf32(Dc[nt], al[0], al[1], al[2], al[3], bh0, bh1);
                mma_tf32(Dc[nt], ah[0], ah[1], ah[2], ah[3], bl0, bl1);
            }
            #pragma unroll
            for (int i = 0; i < 4; i++) a_cur[i] = a_nxt[i];
            #pragma unroll
            for (int nt = 0; nt < 2; nt++) {
                b_cur[nt][0] = b_nxt[nt][0];
                b_cur[nt][1] = b_nxt[nt][1];
            }
        }
        #pragma unroll
        for (int nt = 0; nt < 2; nt++) {
            int n0 = nb + nt * 8 + 2 * t4;
            float bia0 = s[OFF_B1 + n0], bia1 = s[OFF_B1 + n0 + 1];
            *(float2*)(s + OFF_MID + (m0 + gid) * MID_STRIDE + n0) =
                make_float2(Dm[nt][0] + Dc[nt][0] + bia0, Dm[nt][1] + Dc[nt][1] + bia1);
            *(float2*)(s + OFF_MID + (m0 + gid + 8) * MID_STRIDE + n0) =
                make_float2(Dm[nt][2] + Dc[nt][2] + bia0, Dm[nt][3] + Dc[nt][3] + bia1);
        }
    }
    __syncthreads();

    // ---- Stage 2: wgt[64px][144] = mid @ W2 + b2  (3-term tf32, 2 accums; wgt over W1) ----
    // 16 warps: (warp>>2) = m-tile, nset = warp&3 handles ntiles j = nset, nset+4, ... (<18)
    {
        const int m0 = (warp >> 2) * 16;
        const int nset = warp & 3;
        float Dm[5][4], Dc[5][4];
        #pragma unroll
        for (int j = 0; j < 5; j++)
            #pragma unroll
            for (int i = 0; i < 4; i++) { Dm[j][i] = 0.f; Dc[j][i] = 0.f; }

        #pragma unroll
        for (int k0 = 0; k0 < RED; k0 += 8) {
            uint32_t ah[4], al[4];
            tf32_split(s[OFF_MID + (m0 + gid)     * MID_STRIDE + k0 + t4],     ah[0], al[0]);
            tf32_split(s[OFF_MID + (m0 + gid + 8) * MID_STRIDE + k0 + t4],     ah[1], al[1]);
            tf32_split(s[OFF_MID + (m0 + gid)     * MID_STRIDE + k0 + t4 + 4], ah[2], al[2]);
            tf32_split(s[OFF_MID + (m0 + gid + 8) * MID_STRIDE + k0 + t4 + 4], ah[3], al[3]);
            #pragma unroll
            for (int jj = 0; jj < 5; jj++) {
                int j = nset + jj * 4;
                if (j < 18) {
                    int e = j * 8 + gid;
                    uint32_t bh0, bl0, bh1, bl1;
                    tf32_split(s[OFF_W2 + (k0 + t4) * W2_STRIDE + e],     bh0, bl0);
                    tf32_split(s[OFF_W2 + (k0 + t4 + 4) * W2_STRIDE + e], bh1, bl1);
                    mma_tf32(Dm[jj], ah[0], ah[1], ah[2], ah[3], bh0, bh1);
                    mma_tf32(Dc[jj], al[0], al[1], al[2], al[3], bh0, bh1);
                    mma_tf32(Dc[jj], ah[0], ah[1], ah[2], ah[3], bl0, bl1);
                }
            }
        }
        #pragma unroll
        for (int jj = 0; jj < 5; jj++) {
            int j = nset + jj * 4;
            if (j < 18) {
                int e0 = j * 8 + 2 * t4;
                float bb0 = s[OFF_B2 + e0], bb1 = s[OFF_B2 + e0 + 1];
                s[OFF_WGT + (m0 + gid)     * WGT_STRIDE + e0]     = Dm[jj][0] + Dc[jj][0] + bb0;
                s[OFF_WGT + (m0 + gid)     * WGT_STRIDE + e0 + 1] = Dm[jj][1] + Dc[jj][1] + bb1;
                s[OFF_WGT + (m0 + gid + 8) * WGT_STRIDE + e0]     = Dm[jj][2] + Dc[jj][2] + bb0;
                s[OFF_WGT + (m0 + gid + 8) * WGT_STRIDE + e0 + 1] = Dm[jj][3] + Dc[jj][3] + bb1;
            }
        }
    }
    __syncthreads();

    // ---- Stage 3: involution, float4 halo reads, direct STG ----
    // 16 warps: half = warp&1 (4 rows of tile), gset = warp>>1 (2 groups each)
    {
        const int half = warp & 1, gset = warp >> 1;
        const int pr = half * 4 + (lane >> 3), pc = lane & 7;
        const int wbase = OFF_WGT + (pr * 8 + pc) * WGT_STRIDE;
        const int xb = OFF_XH + (pr * 10 + pc) * XH_STRIDE;   // tap (di=0,dj=0)
        float* op = out + ((size_t)((bb * HWDIM + h0 + pr) * HWDIM + (w0 + pc))) * CCH;
        #pragma unroll
        for (int gi = 0; gi < 2; gi++) {
            int g = gset * 2 + gi;
            float wv[9];
            #pragma unroll
            for (int k = 0; k < 9; k++) wv[k] = s[wbase + g * 9 + k];
            int F0g = g * 36;
            int ko0 = F0g >> 6;
            int cs0 = F0g & 63;
            int tc  = 64 - cs0;                    // f4-idx count before boundary
            int di0 = (ko0 * 11) >> 5, dj0 = ko0 - 3 * di0;
            int ko1 = ko0 + 1;
            int di1 = (ko1 * 11) >> 5, dj1 = ko1 - 3 * di1;
            int A0 = xb + (di0 * 10 + dj0) * XH_STRIDE + cs0 * 4;   // + idx*4
            int A1 = xb + (di1 * 10 + dj1) * XH_STRIDE - tc * 4;    // + idx*4 (idx>=tc)
            #pragma unroll
            for (int c = 0; c < 4; c++) {
                float acc[4] = {0.f, 0.f, 0.f, 0.f};
                #pragma unroll
                for (int j = 0; j < 9; j++) {
                    const int idx = c * 9 + j;
                    int addr = ((idx < tc) ? A0 : A1) + idx * 4;
                    const float4 xv = *(const float4*)(s + addr);
                    const int fl = idx * 4;        // float index within group's 144
                    acc[(fl + 0) / 9 - c * 4] += wv[(fl + 0) % 9] * xv.x;
                    acc[(fl + 1) / 9 - c * 4] += wv[(fl + 1) % 9] * xv.y;
                    acc[(fl + 2) / 9 - c * 4] += wv[(fl + 2) % 9] * xv.z;
                    acc[(fl + 3) / 9 - c * 4] += wv[(fl + 3) % 9] * xv.w;
                }
                *(float4*)(op + g * 16 + c * 4) =
                    make_float4(acc[0], acc[1], acc[2], acc[3]);
            }
        }
    }
}

extern "C" void kernel_launch(void* const* d_in, const int* in_sizes, int n_in,
                              void* d_out, int out_size)
{
    (void)in_sizes; (void)n_in; (void)out_size;
    const float* x  = (const float*)d_in[0];
    const float* W1 = (const float*)d_in[1];
    const float* b1 = (const float*)d_in[2];
    const float* W2 = (const float*)d_in[3];
    const float* b2 = (const float*)d_in[4];
    float* out = (float*)d_out;

    cudaFuncSetAttribute(invo_mma_kernel,
                         cudaFuncAttributeMaxDynamicSharedMemorySize, SMEM_BYTES);
    dim3 grid(HWDIM / 8, HWDIM / 8, BATCH);   // (8, 8, 8) = 512 CTAs
    invo_mma_kernel<<<grid, NTHR, SMEM_BYTES>>>(x, W1, b1, W2, b2, out);
}

// round 10
// speedup vs baseline: 1.1085x; 1.1085x over previous
#include <cuda_runtime.h>
#include <cstdint>

#define BATCH  8
#define HWDIM  64
#define CCH    256
#define RED    64
#define EE     144     // K*K*G = 9*16
#define NTHR   512

// ---- smem layout (32-bit word offsets) ----
#define XH_STRIDE  260
#define OFF_XH     0                    // 100*260 = 26000 (fp32)
#define OFF_W1H    26000                // 64*132 = 8448  (bf16x2 words, [n][k/2])
#define W1P_STRIDE 132
#define OFF_W1L    34448                // 8448
#define OFF_WGT    26000                // overlay W1 planes after stage1: 64*145 = 9280
#define WGT_STRIDE 145
#define OFF_W2H    42896                // 144*36 = 5184 ([e][d/2])
#define W2P_STRIDE 36
#define OFF_W2L    48080                // 5184
#define OFF_MID    53264                // 64*68 = 4352 (fp32)
#define MID_STRIDE 68
#define OFF_B1     57616                // 64
#define OFF_B2     57680                // 144
#define SMEM_WORDS 57824
#define SMEM_BYTES (SMEM_WORDS * 4)     // 231296 B <= 227KB limit, 1 CTA/SM

// m16n8k16 bf16 mma: D += A(16x16 row) * B(16x8 col)
__device__ __forceinline__ void mma_bf16(float d[4],
    uint32_t a0, uint32_t a1, uint32_t a2, uint32_t a3,
    uint32_t b0, uint32_t b1)
{
    asm volatile(
        "mma.sync.aligned.m16n8k16.row.col.f32.bf16.bf16.f32 "
        "{%0,%1,%2,%3}, {%4,%5,%6,%7}, {%8,%9}, {%0,%1,%2,%3};"
        : "+f"(d[0]), "+f"(d[1]), "+f"(d[2]), "+f"(d[3])
        : "r"(a0), "r"(a1), "r"(a2), "r"(a3), "r"(b0), "r"(b1));
}

// pack (v0,v1) -> bf16x2 hi (lo half = v0) and bf16x2 residual lo
__device__ __forceinline__ void bf16_split_pair(float v0, float v1,
                                                uint32_t& hi, uint32_t& lo)
{
    uint32_t h;
    asm("cvt.rn.bf16x2.f32 %0, %1, %2;" : "=r"(h) : "f"(v1), "f"(v0));
    float h0 = __uint_as_float(h << 16);
    float h1 = __uint_as_float(h & 0xFFFF0000u);
    float l0 = v0 - h0;
    float l1 = v1 - h1;
    asm("cvt.rn.bf16x2.f32 %0, %1, %2;" : "=r"(lo) : "f"(l1), "f"(l0));
    hi = h;
}

__global__ void __launch_bounds__(NTHR, 1)
invo_mma_kernel(const float* __restrict__ x,
                const float* __restrict__ W1,
                const float* __restrict__ b1,
                const float* __restrict__ W2,
                const float* __restrict__ b2,
                float* __restrict__ out)
{
    extern __shared__ float s[];
    uint32_t* su = (uint32_t*)s;
    const int t  = threadIdx.x;
    const int bb = blockIdx.z;
    const int h0 = blockIdx.y * 8;
    const int w0 = blockIdx.x * 8;

    // ---- Phase 0a: halo 10x10x256 fp32 (zero-padded) ----
    #pragma unroll
    for (int it = 0; it < 13; it++) {
        int i4 = t + it * NTHR;            // 0..6399 float4s
        if (i4 < 6400) {
            int c4 = i4 & 63;
            int sp = i4 >> 6;              // 0..99
            int r  = sp / 10;
            int cl = sp - r * 10;
            int gh = h0 - 1 + r;
            int gw = w0 - 1 + cl;
            float4 v = make_float4(0.f, 0.f, 0.f, 0.f);
            if ((unsigned)gh < HWDIM && (unsigned)gw < HWDIM)
                v = *(const float4*)(x + ((size_t)((bb * HWDIM + gh) * HWDIM + gw) * CCH) + c4 * 4);
            *(float4*)(s + OFF_XH + sp * XH_STRIDE + c4 * 4) = v;
        }
    }
    // ---- Phase 0b: W1 -> bf16 hi/lo planes [n][k/2], transposing ----
    #pragma unroll
    for (int it = 0; it < 4; it++) {
        int u = t + it * NTHR;             // 64 n x 32 k-octets = 2048 units
        int n  = u & 63;
        int ko = u >> 6;                   // k0 = ko*8
        float v[8];
        #pragma unroll
        for (int j = 0; j < 8; j++) v[j] = W1[(ko * 8 + j) * RED + n];
        uint32_t h[4], l[4];
        #pragma unroll
        for (int p = 0; p < 4; p++) bf16_split_pair(v[2*p], v[2*p+1], h[p], l[p]);
        int base = n * W1P_STRIDE + ko * 4;
        *(uint4*)(su + OFF_W1H + base) = make_uint4(h[0], h[1], h[2], h[3]);
        *(uint4*)(su + OFF_W1L + base) = make_uint4(l[0], l[1], l[2], l[3]);
    }
    // ---- Phase 0c: W2 -> bf16 hi/lo planes [e][d/2], transposing ----
    #pragma unroll
    for (int it = 0; it < 3; it++) {
        int u = t + it * NTHR;             // 8 d-octets x 144 e = 1152 units
        if (u < 1152) {
            int dko = u / 144;             // d0 = dko*8
            int e   = u - dko * 144;
            float v[8];
            #pragma unroll
            for (int j = 0; j < 8; j++) v[j] = W2[(dko * 8 + j) * EE + e];
            uint32_t h[4], l[4];
            #pragma unroll
            for (int p = 0; p < 4; p++) bf16_split_pair(v[2*p], v[2*p+1], h[p], l[p]);
            int base = e * W2P_STRIDE + dko * 4;
            *(uint4*)(su + OFF_W2H + base) = make_uint4(h[0], h[1], h[2], h[3]);
            *(uint4*)(su + OFF_W2L + base) = make_uint4(l[0], l[1], l[2], l[3]);
        }
    }
    if (t < RED) s[OFF_B1 + t] = b1[t];
    else if (t >= 128 && t < 128 + EE) s[OFF_B2 + (t - 128)] = b2[t - 128];
    __syncthreads();

    const int warp = t >> 5, lane = t & 31;
    const int gid = lane >> 2, t4 = lane & 3;

    // ---- Stage 1: mid[64px][64] = x @ W1 + b1   (3-term bf16 k16) ----
    // 16 warps: (warp>>2) = m-tile (16 rows), (warp&3) = n-quarter (2 ntiles of 8)
    {
        const int m0 = (warp >> 2) * 16;
        const int nb = (warp & 3) * 16;
        const int px0 = m0 + gid, px1 = px0 + 8;
        const int sp0 = OFF_XH + (((px0 >> 3) + 1) * 10 + (px0 & 7) + 1) * XH_STRIDE;
        const int sp1 = OFF_XH + (((px1 >> 3) + 1) * 10 + (px1 & 7) + 1) * XH_STRIDE;
        float Dm[2][4], Dc[2][4];
        #pragma unroll
        for (int nt = 0; nt < 2; nt++)
            #pragma unroll
            for (int i = 0; i < 4; i++) { Dm[nt][i] = 0.f; Dc[nt][i] = 0.f; }

        #pragma unroll 4
        for (int k0 = 0; k0 < CCH; k0 += 16) {
            float2 p0 = *(const float2*)(s + sp0 + k0 + 2 * t4);
            float2 p1 = *(const float2*)(s + sp1 + k0 + 2 * t4);
            float2 p2 = *(const float2*)(s + sp0 + k0 + 8 + 2 * t4);
            float2 p3 = *(const float2*)(s + sp1 + k0 + 8 + 2 * t4);
            uint32_t ah[4], al[4];
            bf16_split_pair(p0.x, p0.y, ah[0], al[0]);
            bf16_split_pair(p1.x, p1.y, ah[1], al[1]);
            bf16_split_pair(p2.x, p2.y, ah[2], al[2]);
            bf16_split_pair(p3.x, p3.y, ah[3], al[3]);
            #pragma unroll
            for (int nt = 0; nt < 2; nt++) {
                int n = nb + nt * 8 + gid;
                int base = OFF_W1H + n * W1P_STRIDE + (k0 >> 1) + t4;
                uint32_t bh0 = su[base];
                uint32_t bh1 = su[base + 4];
                uint32_t bl0 = su[base + (OFF_W1L - OFF_W1H)];
                uint32_t bl1 = su[base + (OFF_W1L - OFF_W1H) + 4];
                mma_bf16(Dm[nt], ah[0], ah[1], ah[2], ah[3], bh0, bh1);
                mma_bf16(Dc[nt], al[0], al[1], al[2], al[3], bh0, bh1);
                mma_bf16(Dc[nt], ah[0], ah[1], ah[2], ah[3], bl0, bl1);
            }
        }
        #pragma unroll
        for (int nt = 0; nt < 2; nt++) {
            int n0 = nb + nt * 8 + 2 * t4;
            float bia0 = s[OFF_B1 + n0], bia1 = s[OFF_B1 + n0 + 1];
            *(float2*)(s + OFF_MID + (m0 + gid) * MID_STRIDE + n0) =
                make_float2(Dm[nt][0] + Dc[nt][0] + bia0, Dm[nt][1] + Dc[nt][1] + bia1);
            *(float2*)(s + OFF_MID + (m0 + gid + 8) * MID_STRIDE + n0) =
                make_float2(Dm[nt][2] + Dc[nt][2] + bia0, Dm[nt][3] + Dc[nt][3] + bia1);
        }
    }
    __syncthreads();

    // ---- Stage 2: wgt[64px][144] = mid @ W2 + b2  (3-term bf16 k16; wgt over W1 planes) ----
    // 16 warps: (warp>>2) = m-tile, nset = warp&3 handles ntiles j = nset, nset+4, ... (<18)
    {
        const int m0 = (warp >> 2) * 16;
        const int nset = warp & 3;
        float Dm[5][4], Dc[5][4];
        #pragma unroll
        for (int j = 0; j < 5; j++)
            #pragma unroll
            for (int i = 0; i < 4; i++) { Dm[j][i] = 0.f; Dc[j][i] = 0.f; }

        #pragma unroll
        for (int k0 = 0; k0 < RED; k0 += 16) {
            float2 q0 = *(const float2*)(s + OFF_MID + (m0 + gid)     * MID_STRIDE + k0 + 2 * t4);
            float2 q1 = *(const float2*)(s + OFF_MID + (m0 + gid + 8) * MID_STRIDE + k0 + 2 * t4);
            float2 q2 = *(const float2*)(s + OFF_MID + (m0 + gid)     * MID_STRIDE + k0 + 8 + 2 * t4);
            float2 q3 = *(const float2*)(s + OFF_MID + (m0 + gid + 8) * MID_STRIDE + k0 + 8 + 2 * t4);
            uint32_t ah[4], al[4];
            bf16_split_pair(q0.x, q0.y, ah[0], al[0]);
            bf16_split_pair(q1.x, q1.y, ah[1], al[1]);
            bf16_split_pair(q2.x, q2.y, ah[2], al[2]);
            bf16_split_pair(q3.x, q3.y, ah[3], al[3]);
            #pragma unroll
            for (int jj = 0; jj < 5; jj++) {
                int j = nset + jj * 4;
                if (j < 18) {
                    int e = j * 8 + gid;
                    int base = OFF_W2H + e * W2P_STRIDE + (k0 >> 1) + t4;
                    uint32_t bh0 = su[base];
                    uint32_t bh1 = su[base + 4];
                    uint32_t bl0 = su[base + (OFF_W2L - OFF_W2H)];
                    uint32_t bl1 = su[base + (OFF_W2L - OFF_W2H) + 4];
                    mma_bf16(Dm[jj], ah[0], ah[1], ah[2], ah[3], bh0, bh1);
                    mma_bf16(Dc[jj], al[0], al[1], al[2], al[3], bh0, bh1);
                    mma_bf16(Dc[jj], ah[0], ah[1], ah[2], ah[3], bl0, bl1);
                }
            }
        }
        #pragma unroll
        for (int jj = 0; jj < 5; jj++) {
            int j = nset + jj * 4;
            if (j < 18) {
                int e0 = j * 8 + 2 * t4;
                float bb0 = s[OFF_B2 + e0], bb1 = s[OFF_B2 + e0 + 1];
                s[OFF_WGT + (m0 + gid)     * WGT_STRIDE + e0]     = Dm[jj][0] + Dc[jj][0] + bb0;
                s[OFF_WGT + (m0 + gid)     * WGT_STRIDE + e0 + 1] = Dm[jj][1] + Dc[jj][1] + bb1;
                s[OFF_WGT + (m0 + gid + 8) * WGT_STRIDE + e0]     = Dm[jj][2] + Dc[jj][2] + bb0;
                s[OFF_WGT + (m0 + gid + 8) * WGT_STRIDE + e0 + 1] = Dm[jj][3] + Dc[jj][3] + bb1;
            }
        }
    }
    __syncthreads();

    // ---- Stage 3: involution, float4 halo reads, direct STG ----
    // 16 warps: half = warp&1 (4 rows of tile), gset = warp>>1 (2 groups each)
    {
        const int half = warp & 1, gset = warp >> 1;
        const int pr = half * 4 + (lane >> 3), pc = lane & 7;
        const int wbase = OFF_WGT + (pr * 8 + pc) * WGT_STRIDE;
        const int xb = OFF_XH + (pr * 10 + pc) * XH_STRIDE;   // tap (di=0,dj=0)
        float* op = out + ((size_t)((bb * HWDIM + h0 + pr) * HWDIM + (w0 + pc))) * CCH;
        #pragma unroll
        for (int gi = 0; gi < 2; gi++) {
            int g = gset * 2 + gi;
            float wv[9];
            #pragma unroll
            for (int k = 0; k < 9; k++) wv[k] = s[wbase + g * 9 + k];
            int F0g = g * 36;
            int ko0 = F0g >> 6;
            int cs0 = F0g & 63;
            int tc  = 64 - cs0;                    // f4-idx count before boundary
            int di0 = (ko0 * 11) >> 5, dj0 = ko0 - 3 * di0;
            int ko1 = ko0 + 1;
            int di1 = (ko1 * 11) >> 5, dj1 = ko1 - 3 * di1;
            int A0 = xb + (di0 * 10 + dj0) * XH_STRIDE + cs0 * 4;   // + idx*4
            int A1 = xb + (di1 * 10 + dj1) * XH_STRIDE - tc * 4;    // + idx*4 (idx>=tc)
            #pragma unroll
            for (int c = 0; c < 4; c++) {
                float acc[4] = {0.f, 0.f, 0.f, 0.f};
                #pragma unroll
                for (int j = 0; j < 9; j++) {
                    const int idx = c * 9 + j;
                    int addr = ((idx < tc) ? A0 : A1) + idx * 4;
                    const float4 xv = *(const float4*)(s + addr);
                    const int fl = idx * 4;        // float index within group's 144
                    acc[(fl + 0) / 9 - c * 4] += wv[(fl + 0) % 9] * xv.x;
                    acc[(fl + 1) / 9 - c * 4] += wv[(fl + 1) % 9] * xv.y;
                    acc[(fl + 2) / 9 - c * 4] += wv[(fl + 2) % 9] * xv.z;
                    acc[(fl + 3) / 9 - c * 4] += wv[(fl + 3) % 9] * xv.w;
                }
                *(float4*)(op + g * 16 + c * 4) =
                    make_float4(acc[0], acc[1], acc[2], acc[3]);
            }
        }
    }
}

extern "C" void kernel_launch(void* const* d_in, const int* in_sizes, int n_in,
                              void* d_out, int out_size)
{
    (void)in_sizes; (void)n_in; (void)out_size;
    const float* x  = (const float*)d_in[0];
    const float* W1 = (const float*)d_in[1];
    const float* b1 = (const float*)d_in[2];
    const float* W2 = (const float*)d_in[3];
    const float* b2 = (const float*)d_in[4];
    float* out = (float*)d_out;

    cudaFuncSetAttribute(invo_mma_kernel,
                         cudaFuncAttributeMaxDynamicSharedMemorySize, SMEM_BYTES);
    dim3 grid(HWDIM / 8, HWDIM / 8, BATCH);   // (8, 8, 8) = 512 CTAs
    invo_mma_kernel<<<grid, NTHR, SMEM_BYTES>>>(x, W1, b1, W2, b2, out);
}